// round 6
// baseline (speedup 1.0000x reference)
#include <cuda_runtime.h>
#include <math.h>
#include <stdint.h>

// Problem dims
#define B_  256
#define T_  512
#define F_  256
#define H_  1024
#define C_  128

// Tiling
#define NCTA 128     // 4 m-blocks x 32 h-blocks
#define NTH  256     // 8 warps, warp tile m32 x n32
#define MT   64      // batch rows per CTA
#define HB   32      // hidden units per CTA (-> 128 gate cols)
#define KT   32      // K tile
#define NKT1 40      // (F+H)/KT
#define NKT2 64      // (2H)/KT
#define STG  4       // cp.async pipeline stages

// Persistent scratch (no allocations allowed)
__device__ __align__(16) float g_h1[2][B_][H_];
__device__ __align__(16) float g_h2[2][B_][H_];
__device__ __align__(16) float g_y[(long)B_ * T_ * F_];
// Packed, tf32-rounded weights in mma-fragment order:
// [hb][kt][wn][ni][kk2][lane] float4  -> 4096 floats per (hb,kt)
__device__ __align__(16) float g_Wp1[32L * NKT1 * 4096];
__device__ __align__(16) float g_Wp2[32L * NKT2 * 4096];
__device__ unsigned g_cnt = 0;
__device__ volatile unsigned g_gen = 0;

__device__ __forceinline__ unsigned f2tf32(float x) {
    unsigned r;
    asm("cvt.rna.tf32.f32 %0, %1;" : "=r"(r) : "f"(x));
    return r;
}

__device__ __forceinline__ void grid_barrier() {
    __syncthreads();
    if (threadIdx.x == 0) {
        unsigned my = g_gen;
        __threadfence();
        if (atomicAdd(&g_cnt, 1u) == NCTA - 1) {
            g_cnt = 0;
            __threadfence();
            g_gen = my + 1;
        } else {
            while (g_gen == my) { }
            __threadfence();
        }
    }
    __syncthreads();
}

__device__ __forceinline__ void mma_tf32(float* c, const unsigned* a, unsigned b0, unsigned b1) {
    asm volatile(
        "mma.sync.aligned.m16n8k8.row.col.f32.tf32.tf32.f32 "
        "{%0,%1,%2,%3}, {%4,%5,%6,%7}, {%8,%9}, {%0,%1,%2,%3};"
        : "+f"(c[0]), "+f"(c[1]), "+f"(c[2]), "+f"(c[3])
        : "r"(a[0]), "r"(a[1]), "r"(a[2]), "r"(a[3]), "r"(b0), "r"(b1));
}

__device__ __forceinline__ void cp16(uint32_t dst, const void* src) {
    asm volatile("cp.async.cg.shared.global [%0], [%1], 16;" :: "r"(dst), "l"(src));
}
#define CP_COMMIT()  asm volatile("cp.async.commit_group;" ::: "memory")
#define CP_WAIT2()   asm volatile("cp.async.wait_group 2;" ::: "memory")
#define CP_WAIT0()   asm volatile("cp.async.wait_group 0;" ::: "memory")

__device__ __forceinline__ float sigmoidf_(float x) { return 1.f / (1.f + expf(-x)); }

// ---------------- prep kernel: pack weights + convert y (time-invariant work) --------
__global__ void prep_kernel(const float* __restrict__ y,
                            const float* __restrict__ Wih1, const float* __restrict__ Whh1,
                            const float* __restrict__ Wih2, const float* __restrict__ Whh2)
{
    long tid = (long)blockIdx.x * blockDim.x + threadIdx.x;
    long nth = (long)gridDim.x * blockDim.x;

    // y -> tf32-rounded copy
    for (long i = tid; i < (long)B_ * T_ * F_; i += nth)
        g_y[i] = __uint_as_float(f2tf32(y[i]));

    // pack layer 1: one float4 per work item
    const long n1 = 32L * NKT1 * 4 * 4 * 2 * 32;
    for (long i = tid; i < n1; i += nth) {
        int lane = (int)(i & 31); long r = i >> 5;
        int kk2 = (int)(r & 1); r >>= 1;
        int ni  = (int)(r & 3); r >>= 2;
        int wn  = (int)(r & 3); r >>= 2;
        int kt  = (int)(r % NKT1);
        int hb  = (int)(r / NKT1);
        int ncol = wn * 32 + ni * 8 + (lane >> 2);
        long wrow = (long)((ncol >> 5) * H_ + hb * 32 + (ncol & 31));
        int kb = kt * KT + kk2 * 16 + (lane & 3);
        float4 v;
        if (kb < F_) {
            const float* s = Wih1 + wrow * F_ + kb;
            v.x = s[0]; v.y = s[4]; v.z = s[8]; v.w = s[12];
        } else {
            const float* s = Whh1 + wrow * H_ + (kb - F_);
            v.x = s[0]; v.y = s[4]; v.z = s[8]; v.w = s[12];
        }
        uint4 t;
        t.x = f2tf32(v.x); t.y = f2tf32(v.y); t.z = f2tf32(v.z); t.w = f2tf32(v.w);
        ((uint4*)g_Wp1)[i] = t;
    }

    // pack layer 2
    const long n2 = 32L * NKT2 * 4 * 4 * 2 * 32;
    for (long i = tid; i < n2; i += nth) {
        int lane = (int)(i & 31); long r = i >> 5;
        int kk2 = (int)(r & 1); r >>= 1;
        int ni  = (int)(r & 3); r >>= 2;
        int wn  = (int)(r & 3); r >>= 2;
        int kt  = (int)(r % NKT2);
        int hb  = (int)(r / NKT2);
        int ncol = wn * 32 + ni * 8 + (lane >> 2);
        long wrow = (long)((ncol >> 5) * H_ + hb * 32 + (ncol & 31));
        int kb = kt * KT + kk2 * 16 + (lane & 3);
        float4 v;
        if (kb < H_) {
            const float* s = Wih2 + wrow * H_ + kb;
            v.x = s[0]; v.y = s[4]; v.z = s[8]; v.w = s[12];
        } else {
            const float* s = Whh2 + wrow * H_ + (kb - H_);
            v.x = s[0]; v.y = s[4]; v.z = s[8]; v.w = s[12];
        }
        uint4 t;
        t.x = f2tf32(v.x); t.y = f2tf32(v.y); t.z = f2tf32(v.z); t.w = f2tf32(v.w);
        ((uint4*)g_Wp2)[i] = t;
    }
}

// ---------------- main persistent kernel ----------------

// Stage layout (floats): A [64][36] (9216 B) then B packed [4][8][32] float4 (16384 B)
#define ABUF_BYTES   (64 * 36 * 4)
#define STAGE_BYTES  (ABUF_BYTES + 4096 * 4)
#define BIAS_OFF     (STG * STAGE_BYTES)
#define SMEM_BYTES   (BIAS_OFF + 2 * 4 * 32 * 4)

struct LayerCtx {
    const float* a0; long a0s; int ks0;   // tiles from a0: kt < ks0
    const float* a1; long a1s;
    const float4* wpack;                  // per-hb base, float4 units
    int nt;
};

__device__ __forceinline__ void run_layer(
    char* smem, uint32_t smem_u32, const LayerCtx& L,
    const float* __restrict__ biasL, float* cst,
    float* __restrict__ hout, int mb, int hb, bool extra_tanh)
{
    const int tid  = threadIdx.x;
    const int lane = tid & 31, wid = tid >> 5;
    const int wm = wid >> 2, wn = wid & 3;          // 2 x 4 warp grid
    const int r4 = lane >> 2, kc = lane & 3;
    const int lr  = tid >> 3;                        // 0..31 loader row base
    const int lco = (tid & 7) << 2;
    const int hbase = hb * HB;

    // Protect smem stage buffers against the previous layer's epilogue readers.
    __syncthreads();

    const uint32_t dstA = smem_u32 + (lr * 36 + lco) * 4;
    const uint32_t dstB = smem_u32 + ABUF_BYTES + tid * 64;   // 4 float4 per thread

    float acc[2][4][4];
    #pragma unroll
    for (int i = 0; i < 2; i++)
        #pragma unroll
        for (int j = 0; j < 4; j++)
            #pragma unroll
            for (int q = 0; q < 4; q++) acc[i][j][q] = 0.f;

    auto issueT = [&](int kt) {
        uint32_t so = (kt & (STG - 1)) * STAGE_BYTES;
        // A tile
        const float* s; long st;
        if (kt < L.ks0) { s = L.a0 + (long)lr * L.a0s + kt * KT + lco; st = L.a0s; }
        else            { s = L.a1 + (long)lr * L.a1s + (kt - L.ks0) * KT + lco; st = L.a1s; }
        cp16(dstA + so, s);
        cp16(dstA + so + 32 * 36 * 4, s + 32 * st);
        // B tile: linear coalesced copy of 16KB (4 x 16B per thread)
        const float4* wsrc = L.wpack + (long)kt * 1024 + tid * 4;
        uint32_t d = dstB + so;
        cp16(d,      wsrc);
        cp16(d + 16, wsrc + 1);
        cp16(d + 32, wsrc + 2);
        cp16(d + 48, wsrc + 3);
        CP_COMMIT();
    };

    auto mma_tile = [&](const char* stage) {
        // B fragments from smem: 8 conflict-free LDS.128 per thread
        const uint4* Bs = (const uint4*)(stage + ABUF_BYTES) + wn * 256 + lane;
        uint4 bb[8];
        #pragma unroll
        for (int j = 0; j < 8; j++) bb[j] = Bs[32 * j];
        const unsigned* Au = (const unsigned*)stage;
        const int abase = (wm * 32 + r4) * 36 + kc;
        #pragma unroll
        for (int kk = 0; kk < 4; kk++) {
            unsigned a[2][4];
            #pragma unroll
            for (int mi = 0; mi < 2; mi++) {
                int ar = abase + mi * 16 * 36 + kk * 8;
                a[mi][0] = Au[ar];
                a[mi][1] = Au[ar + 8 * 36];
                a[mi][2] = Au[ar + 4];
                a[mi][3] = Au[ar + 8 * 36 + 4];
            }
            #pragma unroll
            for (int ni = 0; ni < 4; ni++) {
                uint4 w = bb[ni * 2 + (kk >> 1)];
                unsigned b0 = (kk & 1) ? w.z : w.x;
                unsigned b1 = (kk & 1) ? w.w : w.y;
                mma_tf32(acc[0][ni], a[0], b0, b1);
                mma_tf32(acc[1][ni], a[1], b0, b1);
            }
        }
    };

    // 4-stage pipeline, prefetch distance 3: wait_group 2 => stage kt landed.
    issueT(0); issueT(1); issueT(2);
    const int nt = L.nt;
    for (int kt = 0; kt < nt; kt++) {
        CP_WAIT2();
        __syncthreads();
        if (kt + 3 < nt) issueT(kt + 3); else CP_COMMIT();
        mma_tile(smem + (kt & (STG - 1)) * STAGE_BYTES);
    }
    CP_WAIT0();
    __syncthreads();   // before reusing smem as gates region

    // Epilogue: gates -> smem, then cell update
    float* gates = (float*)smem;   // [4][64][33]
    #pragma unroll
    for (int mi = 0; mi < 2; mi++)
        #pragma unroll
        for (int ni = 0; ni < 4; ni++) {
            int row = wm * 32 + mi * 16 + r4;
            int col = ni * 8 + kc * 2;
            float* gb = gates + wn * (64 * 33) + row * 33 + col;
            gb[0]          = acc[mi][ni][0];
            gb[1]          = acc[mi][ni][1];
            gb[8 * 33]     = acc[mi][ni][2];
            gb[8 * 33 + 1] = acc[mi][ni][3];
        }
    __syncthreads();

    #pragma unroll
    for (int j = 0; j < 8; j++) {
        int idx = j * NTH + tid;
        int row = idx >> 5, col = idx & 31;
        float gi = gates[0 * 2112 + row * 33 + col] + biasL[0 * 32 + col];
        float gf = gates[1 * 2112 + row * 33 + col] + biasL[1 * 32 + col];
        float gg = gates[2 * 2112 + row * 33 + col] + biasL[2 * 32 + col];
        float go = gates[3 * 2112 + row * 33 + col] + biasL[3 * 32 + col];
        float ii = sigmoidf_(gi);
        float ff = sigmoidf_(gf);
        float g2 = tanhf(gg);
        float oo = sigmoidf_(go);
        float cn = ff * cst[j] + ii * g2;
        cst[j] = cn;
        float h = oo * tanhf(cn);
        if (extra_tanh) h = tanhf(h);
        // store tf32-rounded: identical mma input, skips per-step cvt on A path
        __stcg(&hout[(long)(mb * MT + row) * H_ + hbase + col],
               __uint_as_float(f2tf32(h)));
    }
    // NOTE: no trailing sync; next run_layer starts with __syncthreads().
}

__global__ void __launch_bounds__(NTH, 1) lstm_fused(
    const float* __restrict__ bih1, const float* __restrict__ bhh1,
    const float* __restrict__ bih2, const float* __restrict__ bhh2,
    const float* __restrict__ Wout, const float* __restrict__ bout,
    float* __restrict__ out)
{
    extern __shared__ char smem[];
    uint32_t smem_u32;
    asm("{ .reg .u64 t; cvta.to.shared.u64 t, %1; cvt.u32.u64 %0, t; }"
        : "=r"(smem_u32) : "l"(smem));
    const int tid = threadIdx.x;
    const int mb = blockIdx.x >> 5;   // 0..3
    const int hb = blockIdx.x & 31;   // 0..31
    float* bias_s = (float*)(smem + BIAS_OFF);  // [2][4][32]

    // zero initial h state (buffer 0) for this CTA's slice
    for (int i = tid; i < MT * HB; i += NTH) {
        int r = i >> 5, c = i & 31;
        g_h1[0][mb * MT + r][hb * HB + c] = 0.f;
        g_h2[0][mb * MT + r][hb * HB + c] = 0.f;
    }
    // combined biases, both layers
    {
        int l = tid >> 7;
        int g = (tid >> 5) & 3;
        int u = tid & 31;
        int grow = g * H_ + hb * HB + u;
        bias_s[tid] = (l == 0) ? (bih1[grow] + bhh1[grow]) : (bih2[grow] + bhh2[grow]);
    }
    float c1[8], c2[8];
    #pragma unroll
    for (int j = 0; j < 8; j++) { c1[j] = 0.f; c2[j] = 0.f; }
    __syncthreads();
    grid_barrier();

    const float4* wp1 = (const float4*)g_Wp1 + (long)hb * NKT1 * 1024;
    const float4* wp2 = (const float4*)g_Wp2 + (long)hb * NKT2 * 1024;

    for (int t = 0; t < T_; t++) {
        int rb = t & 1, wb = rb ^ 1;
        {
            LayerCtx L;
            L.a0 = g_y + (long)(mb * MT) * (T_ * F_) + (long)t * F_;
            L.a0s = (long)(T_ * F_);
            L.ks0 = F_ / KT;                 // 8
            L.a1 = &g_h1[rb][mb * MT][0];
            L.a1s = (long)H_;
            L.wpack = wp1;
            L.nt = NKT1;
            run_layer(smem, smem_u32, L, bias_s, c1, &g_h1[wb][0][0], mb, hb, false);
        }
        grid_barrier();
        {
            LayerCtx L;
            L.a0 = &g_h1[wb][mb * MT][0];
            L.a0s = (long)H_;
            L.ks0 = H_ / KT;                 // 32
            L.a1 = &g_h2[rb][mb * MT][0];
            L.a1s = (long)H_;
            L.wpack = wp2;
            L.nt = NKT2;
            run_layer(smem, smem_u32, L, bias_s + 128, c2, &g_h2[wb][0][0], mb, hb, true);
        }
        // no second barrier: hazards ordered by the barrier of step t+1 (validated R5).
    }
    grid_barrier();

    // Output projection: h2 final lives in buffer 0 (T even).
    {
        int gid = blockIdx.x * NTH + tid;
        int b = gid >> 7, cc = gid & 127;
        float acc = __ldg(&bout[cc]);
        const float4* hr = (const float4*)&g_h2[0][b][0];
        const float4* wr = (const float4*)&Wout[(long)cc * H_];
        #pragma unroll 8
        for (int k = 0; k < H_ / 4; k++) {
            float4 hv = __ldcg(hr + k);
            float4 wv = __ldg(wr + k);
            acc += hv.x * wv.x + hv.y * wv.y + hv.z * wv.z + hv.w * wv.w;
        }
        out[gid] = fmaxf(acc, 0.f);
    }
}

extern "C" void kernel_launch(void* const* d_in, const int* in_sizes, int n_in,
                              void* d_out, int out_size) {
    const float* y    = (const float*)d_in[0];
    const float* Wih1 = (const float*)d_in[1];
    const float* Whh1 = (const float*)d_in[2];
    const float* bih1 = (const float*)d_in[3];
    const float* bhh1 = (const float*)d_in[4];
    const float* Wih2 = (const float*)d_in[5];
    const float* Whh2 = (const float*)d_in[6];
    const float* bih2 = (const float*)d_in[7];
    const float* bhh2 = (const float*)d_in[8];
    const float* Wout = (const float*)d_in[9];
    const float* bout = (const float*)d_in[10];
    float* out = (float*)d_out;

    static int smem_set = 0;
    if (!smem_set) {
        cudaFuncSetAttribute(lstm_fused, cudaFuncAttributeMaxDynamicSharedMemorySize, SMEM_BYTES);
        smem_set = 1;
    }

    prep_kernel<<<2048, 256>>>(y, Wih1, Whh1, Wih2, Whh2);
    lstm_fused<<<NCTA, NTH, SMEM_BYTES>>>(bih1, bhh1, bih2, bhh2, Wout, bout, out);
}

// round 9
// speedup vs baseline: 2.3263x; 2.3263x over previous
#include <cuda_runtime.h>
#include <cuda_fp16.h>
#include <math.h>
#include <stdint.h>

// Problem dims
#define B_  256
#define T_  512
#define F_  256
#define H_  1024
#define C_  128

// Tiling
#define NCTA 128     // 4 mb x 32 hb
#define NTH  256     // 8 warps, warp tile m32 x n32
#define MT   64
#define HB   32      // -> 128 gate cols per CTA
#define KT   64      // f16 K tile (4 k-steps of 16)
#define NT1  20      // (F+H)/KT
#define NT2  32      // (2H)/KT

// A smem: row stride 144B (72 halfs) -> conflict-free ldmatrix
#define ASTRIDE_B 144
#define ABUF      (64 * ASTRIDE_B)      // 9216 B per stage, 2 stages

// Persistent scratch
__device__ __align__(16) __half g_h1[2][B_][H_];
__device__ __align__(16) __half g_h2[2][B_][H_];
__device__ __align__(16) __half g_yh[(long)B_ * T_ * F_];
// Packed f16 weights in mma B-fragment order: [hb][tile][wn][j][lane] uint4
__device__ __align__(16) uint4 g_Wp1h[32L * NT1 * 1024];
__device__ __align__(16) uint4 g_Wp2h[32L * NT2 * 1024];
__device__ unsigned g_cnt = 0;
__device__ volatile unsigned g_gen = 0;

__device__ __forceinline__ void grid_barrier() {
    __syncthreads();
    if (threadIdx.x == 0) {
        unsigned my = g_gen;
        __threadfence();
        if (atomicAdd(&g_cnt, 1u) == NCTA - 1) {
            g_cnt = 0;
            __threadfence();
            g_gen = my + 1;
        } else {
            while (g_gen == my) { }
            __threadfence();
        }
    }
    __syncthreads();
}

__device__ __forceinline__ void mma_f16(float* c, const uint32_t* a, uint32_t b0, uint32_t b1) {
    asm volatile(
        "mma.sync.aligned.m16n8k16.row.col.f32.f16.f16.f32 "
        "{%0,%1,%2,%3}, {%4,%5,%6,%7}, {%8,%9}, {%0,%1,%2,%3};"
        : "+f"(c[0]), "+f"(c[1]), "+f"(c[2]), "+f"(c[3])
        : "r"(a[0]), "r"(a[1]), "r"(a[2]), "r"(a[3]), "r"(b0), "r"(b1));
}

__device__ __forceinline__ void ldsm4(uint32_t* a, uint32_t addr) {
    asm volatile("ldmatrix.sync.aligned.m8n8.x4.shared.b16 {%0,%1,%2,%3}, [%4];"
        : "=r"(a[0]), "=r"(a[1]), "=r"(a[2]), "=r"(a[3]) : "r"(addr));
}

__device__ __forceinline__ void cp16(uint32_t dst, const void* src) {
    asm volatile("cp.async.cg.shared.global [%0], [%1], 16;" :: "r"(dst), "l"(src));
}
#define CP_COMMIT()  asm volatile("cp.async.commit_group;" ::: "memory")
#define CP_WAIT0()   asm volatile("cp.async.wait_group 0;" ::: "memory")

__device__ __forceinline__ float fsig(float x) { return 1.f / (1.f + expf(-x)); }

// ---------------- prep: f16 convert y + pack f16 weights into B-fragment order -------
// Fragment math (m16n8k16, row.col): thread lane needs
//   b0 = W[n = wn*32+ni*8+(lane>>2)][k = kb + ks*16 + 2*(lane&3) + {0,1}], b1 = same k+8
// Pack uint4 j = ni*2 + (ks>>1): comps = {b0(ks even), b1(ks even), b0(ks odd), b1(ks odd)}
template <int NT, int KS0>
__device__ void pack_weights(uint4* dst, const float* __restrict__ Wih,
                             const float* __restrict__ Whh, int wih_k, long n_items,
                             long tid, long nth)
{
    for (long i = tid; i < n_items; i += nth) {
        int lane = (int)(i & 31);
        int j    = (int)((i >> 5) & 7);
        int wn   = (int)((i >> 8) & 3);
        int tile = (int)((i >> 10) % NT);
        int hb   = (int)((i >> 10) / NT);
        int kc = lane & 3, nr = lane >> 2;
        int ni = j >> 1, ksa = 2 * (j & 1);
        int ncol = wn * 32 + ni * 8 + nr;
        long grow = (long)((ncol >> 5) * H_ + hb * 32 + (ncol & 31));
        int kb = tile * KT + ksa * 16 + 2 * kc;
        uint32_t comp[4];
        #pragma unroll
        for (int q = 0; q < 4; q++) {
            int k = kb + (q & 1) * 8 + (q >> 1) * 16;
            const float* s = (k < wih_k) ? (Wih + grow * wih_k + k)
                                         : (Whh + grow * H_ + (k - wih_k));
            __half2 h = __floats2half2_rn(s[0], s[1]);
            comp[q] = *(uint32_t*)&h;
        }
        dst[i] = make_uint4(comp[0], comp[1], comp[2], comp[3]);
    }
}

__global__ void prep_kernel(const float* __restrict__ y,
                            const float* __restrict__ Wih1, const float* __restrict__ Whh1,
                            const float* __restrict__ Wih2, const float* __restrict__ Whh2)
{
    long tid = (long)blockIdx.x * blockDim.x + threadIdx.x;
    long nth = (long)gridDim.x * blockDim.x;

    for (long i = tid; i < (long)B_ * T_ * F_ / 2; i += nth) {
        float2 v = ((const float2*)y)[i];
        __half2 h = __floats2half2_rn(v.x, v.y);
        ((__half2*)g_yh)[i] = h;
    }
    pack_weights<NT1, F_>(g_Wp1h, Wih1, Whh1, F_, 32L * NT1 * 1024, tid, nth);
    pack_weights<NT2, H_>(g_Wp2h, Wih2, Whh2, H_, 32L * NT2 * 1024, tid, nth);
}

// ---------------- main persistent kernel ----------------
// smem: A stages 2 x 9216 B; gates epilogue reuses region [4][64][33] f32 = 33792 B
#define BIAS_OFF   (4 * 64 * 33 * 4)
#define SMEM_BYTES (BIAS_OFF + 2 * 4 * 32 * 4)

struct LayerCtx {
    const __half* a0; long a0s; int ks0;   // tiles < ks0 from a0
    const __half* a1;                       // stride H_
    const uint4*  wp;                       // packed fragments, per-hb base
    int nt;
};

__device__ __forceinline__ void run_layer(
    char* smem, uint32_t smem_u32, const LayerCtx& L,
    const float* __restrict__ biasL, float* cst,
    __half* __restrict__ hout, int mb, int hb, bool extra_tanh)
{
    const int tid  = threadIdx.x;
    const int lane = tid & 31, wid = tid >> 5;
    const int wm = wid >> 2, wn = wid & 3;          // 2 m-warps x 4 n-warps
    const int r4 = lane >> 2, kc = lane & 3;
    const int hbase = hb * HB;
    const int lr  = tid >> 2;                        // A loader row 0..63
    const int lc0 = (tid & 3) * 2;                   // 2 x 16B chunks per thread

    __syncthreads();   // protect stage buffers vs previous epilogue readers

    float acc[2][4][4];
    #pragma unroll
    for (int i = 0; i < 2; i++)
        #pragma unroll
        for (int j = 0; j < 4; j++)
            #pragma unroll
            for (int q = 0; q < 4; q++) acc[i][j][q] = 0.f;

    auto issueA = [&](int kt, int stg) {
        uint32_t d = smem_u32 + stg * ABUF + lr * ASTRIDE_B + lc0 * 16;
        const __half* s = (kt < L.ks0) ? (L.a0 + (long)lr * L.a0s + kt * KT)
                                       : (L.a1 + (long)lr * H_ + (kt - L.ks0) * KT);
        s += lc0 * 8;
        cp16(d, s);
        cp16(d + 16, s + 8);
        CP_COMMIT();
    };

    const uint4* wbase = L.wp + (long)wn * 256 + lane;
    auto loadB = [&](int kt, uint4* bb) {
        const uint4* p = wbase + (long)kt * 1024;
        #pragma unroll
        for (int j = 0; j < 8; j++) bb[j] = __ldg(p + 32 * j);
    };

    // ldmatrix lane address components (fixed per thread)
    const uint32_t arow = (uint32_t)((wm * 32 + (lane & 7) + ((lane >> 3) & 1) * 8) * ASTRIDE_B
                                     + (lane >> 4) * 16);

    auto mma_tile = [&](int stg, const uint4* bb) {
        uint32_t a0r = smem_u32 + stg * ABUF + arow;
        uint32_t a1r = a0r + 16 * ASTRIDE_B;
        #pragma unroll
        for (int ks = 0; ks < 4; ks++) {
            uint32_t a0[4], a1[4];
            ldsm4(a0, a0r + ks * 32);
            ldsm4(a1, a1r + ks * 32);
            #pragma unroll
            for (int ni = 0; ni < 4; ni++) {
                uint4 w = bb[ni * 2 + (ks >> 1)];
                uint32_t b0 = (ks & 1) ? w.z : w.x;
                uint32_t b1 = (ks & 1) ? w.w : w.y;
                mma_f16(acc[0][ni], a0, b0, b1);
                mma_f16(acc[1][ni], a1, b0, b1);
            }
        }
    };

    uint4 bb0[8], bb1[8];
    issueA(0, 0);
    loadB(0, bb0);
    const int nt = L.nt;   // even
    for (int kt = 0; kt < nt; kt += 2) {
        CP_WAIT0();
        __syncthreads();
        if (kt + 1 < nt) { issueA(kt + 1, 1); loadB(kt + 1, bb1); }
        mma_tile(0, bb0);
        CP_WAIT0();
        __syncthreads();
        if (kt + 2 < nt) { issueA(kt + 2, 0); loadB(kt + 2, bb0); }
        mma_tile(1, bb1);
    }
    __syncthreads();   // before reusing smem as gates

    // Epilogue: gates -> smem f32, then cell update
    float* gates = (float*)smem;   // [4][64][33]
    #pragma unroll
    for (int mi = 0; mi < 2; mi++)
        #pragma unroll
        for (int ni = 0; ni < 4; ni++) {
            int row = wm * 32 + mi * 16 + r4;
            int col = ni * 8 + kc * 2;
            float* gb = gates + wn * (64 * 33) + row * 33 + col;
            gb[0]          = acc[mi][ni][0];
            gb[1]          = acc[mi][ni][1];
            gb[8 * 33]     = acc[mi][ni][2];
            gb[8 * 33 + 1] = acc[mi][ni][3];
        }
    __syncthreads();

    #pragma unroll
    for (int j = 0; j < 8; j++) {
        int idx = j * NTH + tid;
        int row = idx >> 5, col = idx & 31;
        float gi = gates[0 * 2112 + row * 33 + col] + biasL[0 * 32 + col];
        float gf = gates[1 * 2112 + row * 33 + col] + biasL[1 * 32 + col];
        float gg = gates[2 * 2112 + row * 33 + col] + biasL[2 * 32 + col];
        float go = gates[3 * 2112 + row * 33 + col] + biasL[3 * 32 + col];
        float ii = fsig(gi), ff = fsig(gf);
        float g2 = tanhf(gg), oo = fsig(go);
        float cn = ff * cst[j] + ii * g2;
        cst[j] = cn;
        float h = oo * tanhf(cn);
        if (extra_tanh) h = tanhf(h);
        __half hh = __float2half_rn(h);
        __stcg((unsigned short*)&hout[(long)(mb * MT + row) * H_ + hbase + col],
               __half_as_ushort(hh));
    }
}

__global__ void __launch_bounds__(NTH, 1) lstm_fused(
    const float* __restrict__ bih1, const float* __restrict__ bhh1,
    const float* __restrict__ bih2, const float* __restrict__ bhh2,
    const float* __restrict__ Wout, const float* __restrict__ bout,
    float* __restrict__ out)
{
    extern __shared__ char smem[];
    uint32_t smem_u32;
    asm("{ .reg .u64 t; cvta.to.shared.u64 t, %1; cvt.u32.u64 %0, t; }"
        : "=r"(smem_u32) : "l"(smem));
    const int tid = threadIdx.x;
    const int mb = (int)(blockIdx.x >> 5);   // 0..3
    const int hb = (int)(blockIdx.x & 31);   // 0..31
    float* bias_s = (float*)(smem + BIAS_OFF);

    for (int i = tid; i < MT * HB; i += NTH) {
        int r = i >> 5, c = i & 31;
        g_h1[0][mb * MT + r][hb * HB + c] = __float2half(0.f);
        g_h2[0][mb * MT + r][hb * HB + c] = __float2half(0.f);
    }
    {
        int l = tid >> 7, g = (tid >> 5) & 3, u = tid & 31;
        int grow = g * H_ + hb * HB + u;
        bias_s[tid] = (l == 0) ? (bih1[grow] + bhh1[grow]) : (bih2[grow] + bhh2[grow]);
    }
    float c1[8], c2[8];
    #pragma unroll
    for (int j = 0; j < 8; j++) { c1[j] = 0.f; c2[j] = 0.f; }
    __syncthreads();
    grid_barrier();

    const uint4* wp1 = g_Wp1h + (long)hb * NT1 * 1024;
    const uint4* wp2 = g_Wp2h + (long)hb * NT2 * 1024;

    for (int t = 0; t < T_; t++) {
        int rb = t & 1, wb = rb ^ 1;
        {
            LayerCtx L;
            L.a0 = g_yh + (long)(mb * MT) * (T_ * F_) + (long)t * F_;
            L.a0s = (long)(T_ * F_);
            L.ks0 = F_ / KT;                 // 4
            L.a1 = &g_h1[rb][mb * MT][0];
            L.wp = wp1;
            L.nt = NT1;
            run_layer(smem, smem_u32, L, bias_s, c1, &g_h1[wb][0][0], mb, hb, false);
        }
        grid_barrier();
        {
            LayerCtx L;
            L.a0 = &g_h1[wb][mb * MT][0];
            L.a0s = (long)H_;
            L.ks0 = H_ / KT;                 // 16
            L.a1 = &g_h2[rb][mb * MT][0];
            L.wp = wp2;
            L.nt = NT2;
            run_layer(smem, smem_u32, L, bias_s + 128, c2, &g_h2[wb][0][0], mb, hb, true);
        }
        // single barrier per step: remaining hazards ordered by step t+1's barrier (R5)
    }
    grid_barrier();

    // Output projection: h2 final in buffer 0 (T even). One output per thread.
    {
        int gid = (int)blockIdx.x * NTH + tid;
        int b = gid >> 7, cc = gid & 127;
        float acc = __ldg(&bout[cc]);
        const __half* hr = &g_h2[0][b][0];
        const float*  wr = &Wout[(long)cc * H_];
        #pragma unroll 4
        for (int k = 0; k < H_ / 8; k++) {
            uint4 hk = __ldcg((const uint4*)(hr + k * 8));
            const __half2* hp = (const __half2*)&hk;
            float4 w0 = __ldg((const float4*)(wr + k * 8));
            float4 w1 = __ldg((const float4*)(wr + k * 8 + 4));
            float2 p0 = __half22float2(hp[0]);
            float2 p1 = __half22float2(hp[1]);
            float2 p2 = __half22float2(hp[2]);
            float2 p3 = __half22float2(hp[3]);
            acc += p0.x * w0.x + p0.y * w0.y + p1.x * w0.z + p1.y * w0.w;
            acc += p2.x * w1.x + p2.y * w1.y + p3.x * w1.z + p3.y * w1.w;
        }
        out[gid] = fmaxf(acc, 0.f);
    }
}

extern "C" void kernel_launch(void* const* d_in, const int* in_sizes, int n_in,
                              void* d_out, int out_size) {
    const float* y    = (const float*)d_in[0];
    const float* Wih1 = (const float*)d_in[1];
    const float* Whh1 = (const float*)d_in[2];
    const float* bih1 = (const float*)d_in[3];
    const float* bhh1 = (const float*)d_in[4];
    const float* Wih2 = (const float*)d_in[5];
    const float* Whh2 = (const float*)d_in[6];
    const float* bih2 = (const float*)d_in[7];
    const float* bhh2 = (const float*)d_in[8];
    const float* Wout = (const float*)d_in[9];
    const float* bout = (const float*)d_in[10];
    float* out = (float*)d_out;

    prep_kernel<<<2048, 256>>>(y, Wih1, Whh1, Wih2, Whh2);
    lstm_fused<<<NCTA, NTH, SMEM_BYTES>>>(bih1, bhh1, bih2, bhh2, Wout, bout, out);
}

// round 10
// speedup vs baseline: 2.3973x; 1.0306x over previous
#include <cuda_runtime.h>
#include <cuda_fp16.h>
#include <math.h>
#include <stdint.h>

// Problem dims
#define B_  256
#define T_  512
#define F_  256
#define H_  1024
#define C_  128

// Tiling: 256 CTAs = 4 mb (64 rows) x 64 hb (16 h-units -> 64 gate cols), 2 CTAs/SM
#define NCTA 256
#define NTH  256     // 8 warps: 2 m-warps x 4 n-warps, warp tile m32 x n16
#define MT   64
#define HB   16
#define KT   64      // f16 K tile (4 k-steps of 16)
#define NT1  20      // (F+H)/KT
#define NT2  32      // (2H)/KT
#define NSTG 4

// A smem: row stride 144B (72 halfs) -> conflict-free ldmatrix
#define ASTRIDE_B 144
#define ABUF      (64 * ASTRIDE_B)      // 9216 B per stage
#define BIAS_OFF  (NSTG * ABUF)         // gates epilogue [4][64][17]f32=17408 fits in stages
#define SMEM_BYTES (BIAS_OFF + 128 * 4)

// Persistent scratch
__device__ __align__(16) __half g_h1[2][B_][H_];
__device__ __align__(16) __half g_h2[2][B_][H_];
__device__ __align__(16) __half g_yh[(long)B_ * T_ * F_];
// Packed f16 weights in mma B-fragment order: [hb][tile][wn][j][lane] uint4 (512/tile)
__device__ __align__(16) uint4 g_Wp1h[64L * NT1 * 512];
__device__ __align__(16) uint4 g_Wp2h[64L * NT2 * 512];
__device__ unsigned g_cnt = 0;
__device__ volatile unsigned g_gen = 0;

__device__ __forceinline__ void grid_barrier() {
    __syncthreads();
    if (threadIdx.x == 0) {
        unsigned my = g_gen;
        __threadfence();
        if (atomicAdd(&g_cnt, 1u) == NCTA - 1) {
            g_cnt = 0;
            __threadfence();
            g_gen = my + 1;
        } else {
            while (g_gen == my) { }
            __threadfence();
        }
    }
    __syncthreads();
}

__device__ __forceinline__ void mma_f16(float* c, const uint32_t* a, uint32_t b0, uint32_t b1) {
    asm volatile(
        "mma.sync.aligned.m16n8k16.row.col.f32.f16.f16.f32 "
        "{%0,%1,%2,%3}, {%4,%5,%6,%7}, {%8,%9}, {%0,%1,%2,%3};"
        : "+f"(c[0]), "+f"(c[1]), "+f"(c[2]), "+f"(c[3])
        : "r"(a[0]), "r"(a[1]), "r"(a[2]), "r"(a[3]), "r"(b0), "r"(b1));
}

__device__ __forceinline__ void ldsm4(uint32_t* a, uint32_t addr) {
    asm volatile("ldmatrix.sync.aligned.m8n8.x4.shared.b16 {%0,%1,%2,%3}, [%4];"
        : "=r"(a[0]), "=r"(a[1]), "=r"(a[2]), "=r"(a[3]) : "r"(addr));
}

__device__ __forceinline__ void cp16(uint32_t dst, const void* src) {
    asm volatile("cp.async.cg.shared.global [%0], [%1], 16;" :: "r"(dst), "l"(src));
}
#define CP_COMMIT()  asm volatile("cp.async.commit_group;" ::: "memory")
#define CP_WAIT2()   asm volatile("cp.async.wait_group 2;" ::: "memory")
#define CP_WAIT0()   asm volatile("cp.async.wait_group 0;" ::: "memory")

__device__ __forceinline__ float fsig(float x) { return 1.f / (1.f + expf(-x)); }

// ---------------- prep: f16 convert y + pack weights into B-fragment order ----------
// m16n8k16 row.col B fragment: lane needs b0 = W[n=nr][kb+2kc,+1], b1 = same k+8.
// CTA col c (0..63): gate = c>>4, unit = c&15. ncol = wn*16 + ni*8 + nr, ni in {0,1}.
// uint4 j = ni*2 + (ks>>1): {b0 ks even, b1 ks even, b0 ks odd, b1 ks odd}
__device__ void pack_weights(uint4* dst, const float* __restrict__ Wih,
                             const float* __restrict__ Whh, int wih_k, int NT,
                             long n_items, long tid, long nth)
{
    for (long i = tid; i < n_items; i += nth) {
        int lane = (int)(i & 31);
        int j    = (int)((i >> 5) & 3);
        int wn   = (int)((i >> 7) & 3);
        int tile = (int)((i >> 9) % NT);
        int hb   = (int)((i >> 9) / NT);
        int kc = lane & 3, nr = lane >> 2;
        int ni = j >> 1, ksa = 2 * (j & 1);
        int ncol = wn * 16 + ni * 8 + nr;
        long grow = (long)((ncol >> 4) * H_ + hb * 16 + (ncol & 15));
        int kb = tile * KT + ksa * 16 + 2 * kc;
        uint32_t comp[4];
        #pragma unroll
        for (int q = 0; q < 4; q++) {
            int k = kb + (q & 1) * 8 + (q >> 1) * 16;
            const float* s = (k < wih_k) ? (Wih + grow * wih_k + k)
                                         : (Whh + grow * H_ + (k - wih_k));
            __half2 h = __floats2half2_rn(s[0], s[1]);
            comp[q] = *(uint32_t*)&h;
        }
        dst[i] = make_uint4(comp[0], comp[1], comp[2], comp[3]);
    }
}

__global__ void prep_kernel(const float* __restrict__ y,
                            const float* __restrict__ Wih1, const float* __restrict__ Whh1,
                            const float* __restrict__ Wih2, const float* __restrict__ Whh2)
{
    long tid = (long)blockIdx.x * blockDim.x + threadIdx.x;
    long nth = (long)gridDim.x * blockDim.x;

    for (long i = tid; i < (long)B_ * T_ * F_ / 2; i += nth) {
        float2 v = ((const float2*)y)[i];
        __half2 h = __floats2half2_rn(v.x, v.y);
        ((__half2*)g_yh)[i] = h;
    }
    pack_weights(g_Wp1h, Wih1, Whh1, F_, NT1, 64L * NT1 * 512, tid, nth);
    pack_weights(g_Wp2h, Wih2, Whh2, H_, NT2, 64L * NT2 * 512, tid, nth);
}

// ---------------- main persistent kernel ----------------

struct LayerCtx {
    const __half* a0; long a0s; int ks0;   // tiles < ks0 from a0
    const __half* a1;                       // stride H_
    const uint4*  wp;                       // packed fragments, per-hb base
    int nt;
};

__device__ __forceinline__ void run_layer(
    char* smem, uint32_t smem_u32, const LayerCtx& L,
    const float* __restrict__ biasL, float* cst,
    __half* __restrict__ hout, int mb, int hb, bool extra_tanh)
{
    const int tid  = threadIdx.x;
    const int lane = tid & 31, wid = tid >> 5;
    const int wm = wid >> 2, wn = wid & 3;          // 2 m-warps x 4 n-warps (wn = gate)
    const int r4 = lane >> 2, kc = lane & 3;
    const int lr  = tid >> 2;                        // A loader row 0..63
    const int lc0 = (tid & 3) * 2;                   // 2 x 16B chunks per thread

    __syncthreads();   // protect stage buffers vs previous epilogue readers

    float acc[2][2][4];
    #pragma unroll
    for (int i = 0; i < 2; i++)
        #pragma unroll
        for (int j = 0; j < 2; j++)
            #pragma unroll
            for (int q = 0; q < 4; q++) acc[i][j][q] = 0.f;

    auto issueA = [&](int kt) {
        uint32_t d = smem_u32 + (kt & (NSTG - 1)) * ABUF + lr * ASTRIDE_B + lc0 * 16;
        const __half* s = (kt < L.ks0) ? (L.a0 + (long)lr * L.a0s + kt * KT)
                                       : (L.a1 + (long)lr * H_ + (kt - L.ks0) * KT);
        s += lc0 * 8;
        cp16(d, s);
        cp16(d + 16, s + 8);
        CP_COMMIT();
    };

    const uint4* wbase = L.wp + (long)wn * 128 + lane;

    // ldmatrix lane address (fixed per thread)
    const uint32_t arow = (uint32_t)((wm * 32 + (lane & 7) + ((lane >> 3) & 1) * 8) * ASTRIDE_B
                                     + (lane >> 4) * 16);

    // 4-stage pipeline, distance 3; wait_group 2 => stage kt landed, kt+1/kt+2 in flight.
    issueA(0); issueA(1); issueA(2);
    const int nt = L.nt;
    for (int kt = 0; kt < nt; kt++) {
        // JIT B fragments: issue LDGs before the wait so latency overlaps it
        uint4 bb[4];
        {
            const uint4* p = wbase + (long)kt * 512;
            #pragma unroll
            for (int j = 0; j < 4; j++) bb[j] = __ldg(p + 32 * j);
        }
        CP_WAIT2();
        __syncthreads();
        if (kt + 3 < nt) issueA(kt + 3); else CP_COMMIT();
        uint32_t a0r = smem_u32 + (kt & (NSTG - 1)) * ABUF + arow;
        uint32_t a1r = a0r + 16 * ASTRIDE_B;
        #pragma unroll
        for (int ks = 0; ks < 4; ks++) {
            uint32_t a0[4], a1[4];
            ldsm4(a0, a0r + ks * 32);
            ldsm4(a1, a1r + ks * 32);
            #pragma unroll
            for (int ni = 0; ni < 2; ni++) {
                uint4 w = bb[ni * 2 + (ks >> 1)];
                uint32_t b0 = (ks & 1) ? w.z : w.x;
                uint32_t b1 = (ks & 1) ? w.w : w.y;
                mma_f16(acc[0][ni], a0, b0, b1);
                mma_f16(acc[1][ni], a1, b0, b1);
            }
        }
    }
    CP_WAIT0();
    __syncthreads();   // before reusing smem as gates

    // Epilogue: gates -> smem f32 [4 gate][64 row][17], then cell update
    float* gates = (float*)smem;
    #pragma unroll
    for (int mi = 0; mi < 2; mi++)
        #pragma unroll
        for (int ni = 0; ni < 2; ni++) {
            int row = wm * 32 + mi * 16 + r4;
            int u = ni * 8 + kc * 2;          // unit within gate (gate == wn)
            float* gb = gates + wn * (64 * 17) + row * 17 + u;
            gb[0]          = acc[mi][ni][0];
            gb[1]          = acc[mi][ni][1];
            gb[8 * 17]     = acc[mi][ni][2];
            gb[8 * 17 + 1] = acc[mi][ni][3];
        }
    __syncthreads();

    #pragma unroll
    for (int j = 0; j < 4; j++) {
        int idx = j * NTH + tid;
        int row = idx >> 4, col = idx & 15;
        float gi = gates[0 * 1088 + row * 17 + col] + biasL[0 * 16 + col];
        float gf = gates[1 * 1088 + row * 17 + col] + biasL[1 * 16 + col];
        float gg = gates[2 * 1088 + row * 17 + col] + biasL[2 * 16 + col];
        float go = gates[3 * 1088 + row * 17 + col] + biasL[3 * 16 + col];
        float ii = fsig(gi), ff = fsig(gf);
        float g2 = tanhf(gg), oo = fsig(go);
        float cn = ff * cst[j] + ii * g2;
        cst[j] = cn;
        float h = oo * tanhf(cn);
        if (extra_tanh) h = tanhf(h);
        __half hh = __float2half_rn(h);
        __stcg((unsigned short*)&hout[(long)(mb * MT + row) * H_ + hb * HB + col],
               __half_as_ushort(hh));
    }
}

__global__ void __launch_bounds__(NTH, 2) lstm_fused(
    const float* __restrict__ bih1, const float* __restrict__ bhh1,
    const float* __restrict__ bih2, const float* __restrict__ bhh2,
    const float* __restrict__ Wout, const float* __restrict__ bout,
    float* __restrict__ out)
{
    extern __shared__ char smem[];
    uint32_t smem_u32;
    asm("{ .reg .u64 t; cvta.to.shared.u64 t, %1; cvt.u32.u64 %0, t; }"
        : "=r"(smem_u32) : "l"(smem));
    const int tid = threadIdx.x;
    const int mb = (int)(blockIdx.x >> 6);   // 0..3
    const int hb = (int)(blockIdx.x & 63);   // 0..63
    float* bias_s = (float*)(smem + BIAS_OFF);

    for (int i = tid; i < MT * HB; i += NTH) {
        int r = i >> 4, c = i & 15;
        g_h1[0][mb * MT + r][hb * HB + c] = __float2half(0.f);
        g_h2[0][mb * MT + r][hb * HB + c] = __float2half(0.f);
    }
    if (tid < 128) {
        int l = tid >> 6, g = (tid >> 4) & 3, u = tid & 15;
        int grow = g * H_ + hb * HB + u;
        bias_s[tid] = (l == 0) ? (bih1[grow] + bhh1[grow]) : (bih2[grow] + bhh2[grow]);
    }
    float c1[4], c2[4];
    #pragma unroll
    for (int j = 0; j < 4; j++) { c1[j] = 0.f; c2[j] = 0.f; }
    __syncthreads();
    grid_barrier();

    const uint4* wp1 = g_Wp1h + (long)hb * NT1 * 512;
    const uint4* wp2 = g_Wp2h + (long)hb * NT2 * 512;

    for (int t = 0; t < T_; t++) {
        int rb = t & 1, wb = rb ^ 1;
        {
            LayerCtx L;
            L.a0 = g_yh + (long)(mb * MT) * (T_ * F_) + (long)t * F_;
            L.a0s = (long)(T_ * F_);
            L.ks0 = F_ / KT;                 // 4
            L.a1 = &g_h1[rb][mb * MT][0];
            L.wp = wp1;
            L.nt = NT1;
            run_layer(smem, smem_u32, L, bias_s, c1, &g_h1[wb][0][0], mb, hb, false);
        }
        grid_barrier();
        {
            LayerCtx L;
            L.a0 = &g_h1[wb][mb * MT][0];
            L.a0s = (long)H_;
            L.ks0 = H_ / KT;                 // 16
            L.a1 = &g_h2[rb][mb * MT][0];
            L.wp = wp2;
            L.nt = NT2;
            run_layer(smem, smem_u32, L, bias_s + 64, c2, &g_h2[wb][0][0], mb, hb, true);
        }
        // single barrier per step: remaining hazards ordered by step t+1's barrier (R5)
    }
    grid_barrier();

    // Output projection: h2 final in buffer 0 (T even). First 128 CTAs, 1 elem/thread.
    {
        int gid = (int)blockIdx.x * NTH + tid;
        if (gid < B_ * C_) {
            int b = gid >> 7, cc = gid & 127;
            float acc = __ldg(&bout[cc]);
            const __half* hr = &g_h2[0][b][0];
            const float*  wr = &Wout[(long)cc * H_];
            #pragma unroll 4
            for (int k = 0; k < H_ / 8; k++) {
                uint4 hk = __ldcg((const uint4*)(hr + k * 8));
                const __half2* hp = (const __half2*)&hk;
                float4 w0 = __ldg((const float4*)(wr + k * 8));
                float4 w1 = __ldg((const float4*)(wr + k * 8 + 4));
                float2 p0 = __half22float2(hp[0]);
                float2 p1 = __half22float2(hp[1]);
                float2 p2 = __half22float2(hp[2]);
                float2 p3 = __half22float2(hp[3]);
                acc += p0.x * w0.x + p0.y * w0.y + p1.x * w0.z + p1.y * w0.w;
                acc += p2.x * w1.x + p2.y * w1.y + p3.x * w1.z + p3.y * w1.w;
            }
            out[gid] = fmaxf(acc, 0.f);
        }
    }
}

extern "C" void kernel_launch(void* const* d_in, const int* in_sizes, int n_in,
                              void* d_out, int out_size) {
    const float* y    = (const float*)d_in[0];
    const float* Wih1 = (const float*)d_in[1];
    const float* Whh1 = (const float*)d_in[2];
    const float* bih1 = (const float*)d_in[3];
    const float* bhh1 = (const float*)d_in[4];
    const float* Wih2 = (const float*)d_in[5];
    const float* Whh2 = (const float*)d_in[6];
    const float* bih2 = (const float*)d_in[7];
    const float* bhh2 = (const float*)d_in[8];
    const float* Wout = (const float*)d_in[9];
    const float* bout = (const float*)d_in[10];
    float* out = (float*)d_out;

    prep_kernel<<<2048, 256>>>(y, Wih1, Whh1, Wih2, Whh2);
    lstm_fused<<<NCTA, NTH, SMEM_BYTES>>>(bih1, bhh1, bih2, bhh2, Wout, bout, out);
}